// round 13
// baseline (speedup 1.0000x reference)
#include <cuda_runtime.h>
#include <cuda_fp16.h>
#include <cstdint>

#define BB 2
#define SS 2048
#define EE 512
#define HH 8
#define DD 64
#define MT (BB*SS)     // 4096 rows
#define NPROJ 1536     // fused P|C|S output width
#define MAXCH 16       // max stored children per node

// ---------------------------------------------------------------------------
// Scratch (device globals: allocation-free per harness rules)
// ---------------------------------------------------------------------------
__device__ float  g_PCS[MT*NPROJ];                 // P|C|S fused, stride 1536
__device__ __align__(16) __half g_xh [MT*EE];
__device__ __align__(16) __half g_aoh[MT*EE];
__device__ __align__(16) __half g_Wt [4][EE*EE];   // transposed [N][K], fp16
__device__ float  g_bcat[NPROJ];                   // bp|bc|bs
__device__ int    g_nbr [MT*MAXCH];                // children lists (unordered)
__device__ int    g_ncnt[MT];                      // children counts (self-zeroing)

// ---------------------------------------------------------------------------
// Helpers (base-target PTX only: ldmatrix / mma.sync / cp.async)
// ---------------------------------------------------------------------------
__device__ __forceinline__ uint32_t smem_u32(const void* p) {
    uint32_t a;
    asm("{ .reg .u64 t; cvta.to.shared.u64 t, %1; cvt.u32.u64 %0, t; }"
        : "=r"(a) : "l"(p));
    return a;
}
__device__ __forceinline__ void ldsm4(uint32_t* r, uint32_t addr) {
    asm volatile("ldmatrix.sync.aligned.m8n8.x4.shared.b16 {%0,%1,%2,%3}, [%4];"
        : "=r"(r[0]), "=r"(r[1]), "=r"(r[2]), "=r"(r[3]) : "r"(addr));
}
__device__ __forceinline__ void mma16816(float* d, const uint32_t* a,
                                         uint32_t b0, uint32_t b1) {
    asm volatile("mma.sync.aligned.m16n8k16.row.col.f32.f16.f16.f32 "
        "{%0,%1,%2,%3}, {%4,%5,%6,%7}, {%8,%9}, {%0,%1,%2,%3};"
        : "+f"(d[0]), "+f"(d[1]), "+f"(d[2]), "+f"(d[3])
        : "r"(a[0]), "r"(a[1]), "r"(a[2]), "r"(a[3]), "r"(b0), "r"(b1));
}
__device__ __forceinline__ void cpasync16(uint32_t saddr, const void* g) {
    asm volatile("cp.async.cg.shared.global [%0], [%1], 16;"
                 :: "r"(saddr), "l"(g) : "memory");
}
#define CP_COMMIT() asm volatile("cp.async.commit_group;" ::: "memory")
#define CP_WAIT(n)  asm volatile("cp.async.wait_group %0;" :: "n"(n) : "memory")

// ---------------------------------------------------------------------------
// Combined prep: blocks [0,1024) transpose the 4 weights to fp16 [N][K];
// blocks [1024,2048) convert x to fp16; blocks [2048,2064) scatter children.
// (g_ncnt is zero on entry: zero-initialized at load, re-zeroed by tree_attn
//  at the end of every launch.)
// ---------------------------------------------------------------------------
__global__ __launch_bounds__(256) void prep_all(
    const float* __restrict__ Wp, const float* __restrict__ Wc,
    const float* __restrict__ Ws, const float* __restrict__ Wo,
    const float* __restrict__ bp, const float* __restrict__ bc,
    const float* __restrict__ bs, const float* __restrict__ x,
    const int* __restrict__ parent,
    __half* __restrict__ Wt, float* __restrict__ bcat,
    __half* __restrict__ xh)
{
    const int bid = blockIdx.x;
    const int tid = threadIdx.x;
    if (bid < 1024) {
        __shared__ float t[32][33];
        const int w    = bid >> 8;
        const int tile = bid & 255;
        const int k0 = (tile & 15) * 32, n0 = (tile >> 4) * 32;
        const float* W = (w == 0) ? Wp : (w == 1) ? Wc : (w == 2) ? Ws : Wo;
        __half* out = Wt + (size_t)w * EE * EE;
        const int tx = tid & 31;
        const int ty = tid >> 5;

        for (int j = ty; j < 32; j += 8)
            t[j][tx] = W[(size_t)(k0 + j) * EE + n0 + tx];
        __syncthreads();
        for (int j = ty; j < 32; j += 8)
            out[(size_t)(n0 + j) * EE + k0 + tx] = __float2half_rn(t[tx][j]);

        if (bid < 6) {
            int i = bid * 256 + tid;
            bcat[i] = (i < 512) ? bp[i] : (i < 1024) ? bc[i - 512] : bs[i - 1024];
        }
    } else if (bid < 2048) {
        const int base = (bid - 1024) * 512 + tid;
        #pragma unroll
        for (int r = 0; r < 2; r++) {
            int i = base + r * 256;
            float4 v = reinterpret_cast<const float4*>(x)[i];
            __half2 h01 = __halves2half2(__float2half_rn(v.x), __float2half_rn(v.y));
            __half2 h23 = __halves2half2(__float2half_rn(v.z), __float2half_rn(v.w));
            reinterpret_cast<__half2*>(xh)[i*2+0] = h01;
            reinterpret_cast<__half2*>(xh)[i*2+1] = h23;
        }
    } else {
        // Child scatter: node u = (b, m); append m to parent's child list.
        // Order within a list is nondeterministic (atomics) — tree_attn
        // sorts each list, restoring full determinism.
        const int u = (bid - 2048) * 256 + tid;     // 0..4095
        const int b = u >> 11;
        const int m = u & (SS - 1);
        const int p = parent[u];
        const int idx = b * SS + p;
        int pos = atomicAdd(&g_ncnt[idx], 1);
        if (pos < MAXCH) g_nbr[idx * MAXCH + pos] = m;
    }
}

// ---------------------------------------------------------------------------
// mma.sync fp16 GEMM (R8 config, FROZEN): Out[M,Nst] = A[M,512] @ Wt^T + bias
// ---------------------------------------------------------------------------
#define GPITCH 144

template<int TM>
__global__ __launch_bounds__(256) void gemm_mma(
    const __half* __restrict__ Ah, const __half* __restrict__ Bh,
    const float* __restrict__ bias, float* __restrict__ Out, int Nst)
{
    constexpr int CTA_M  = 32 * TM;
    constexpr int TILE_A = CTA_M * GPITCH;
    constexpr int ROWS   = CTA_M + 128;
    constexpr int STAGE  = ROWS * GPITCH;
    constexpr int ITERS  = (ROWS * 8) / 256;

    extern __shared__ char smem[];
    const uint32_t sb = smem_u32(smem);
    const int tid  = threadIdx.x;
    const int wid  = tid >> 5;
    const int lane = tid & 31;
    const int wm   = wid & 1;
    const int wn   = wid >> 1;
    const int bm   = blockIdx.y * CTA_M;
    const int bn   = blockIdx.x * 128;

    float acc[TM][4][4];
    #pragma unroll
    for (int i = 0; i < TM; i++)
        #pragma unroll
        for (int j = 0; j < 4; j++)
            #pragma unroll
            for (int q = 0; q < 4; q++) acc[i][j][q] = 0.0f;

    auto load_stage = [&](int stg, int c) {
        const int kb = c * 64;
        #pragma unroll
        for (int j = 0; j < ITERS; j++) {
            int u   = j * 256 + tid;
            int row = u >> 3, cc = u & 7;
            bool isA = (row < CTA_M);
            uint32_t sa = sb + stg * STAGE
                        + (isA ? row * GPITCH : TILE_A + (row - CTA_M) * GPITCH)
                        + cc * 16;
            const __half* gp = isA ? Ah + (size_t)(bm + row) * EE
                                   : Bh + (size_t)(bn + row - CTA_M) * EE;
            cpasync16(sa, gp + kb + cc * 8);
        }
        CP_COMMIT();
    };

    load_stage(0, 0);
    load_stage(1, 1);

    const uint32_t lrow = (uint32_t)(lane & 15);
    const uint32_t lcol = (uint32_t)((lane >> 4) << 4);

    int stage = 0;
    for (int c = 0; c < 8; c++) {
        if (c < 6)      { load_stage((stage + 2) % 3, c + 2); CP_WAIT(2); }
        else if (c == 6){ CP_WAIT(1); }
        else            { CP_WAIT(0); }
        __syncthreads();

        const uint32_t stg = sb + stage * STAGE;
        const uint32_t abase = stg + (wm * 16 * TM + lrow) * GPITCH + lcol;
        const uint32_t bbase = stg + TILE_A + (wn * 32 + lrow) * GPITCH + lcol;

        uint32_t af[2][TM][4], bf[2][2][4];
        #pragma unroll
        for (int tm = 0; tm < TM; tm++) ldsm4(af[0][tm], abase + tm * 16 * GPITCH);
        #pragma unroll
        for (int t2 = 0; t2 < 2; t2++)  ldsm4(bf[0][t2], bbase + t2 * 16 * GPITCH);

        #pragma unroll
        for (int kk = 0; kk < 4; kk++) {
            const int cur = kk & 1, nxt = cur ^ 1;
            if (kk < 3) {
                const uint32_t ko = (kk + 1) * 32;
                #pragma unroll
                for (int tm = 0; tm < TM; tm++)
                    ldsm4(af[nxt][tm], abase + tm * 16 * GPITCH + ko);
                #pragma unroll
                for (int t2 = 0; t2 < 2; t2++)
                    ldsm4(bf[nxt][t2], bbase + t2 * 16 * GPITCH + ko);
            }
            #pragma unroll
            for (int tm = 0; tm < TM; tm++)
                #pragma unroll
                for (int tn = 0; tn < 4; tn++) {
                    const int t2 = tn >> 1, hi = tn & 1;
                    mma16816(acc[tm][tn], af[cur][tm],
                             bf[cur][t2][hi], bf[cur][t2][2 + hi]);
                }
        }
        __syncthreads();
        stage = (stage == 2) ? 0 : stage + 1;
    }

    const int r0 = bm + wm * 16 * TM + (lane >> 2);
    const int c0 = bn + wn * 32 + ((lane & 3) << 1);
    #pragma unroll
    for (int tm = 0; tm < TM; tm++) {
        #pragma unroll
        for (int tn = 0; tn < 4; tn++) {
            int row = r0 + tm * 16;
            int col = c0 + tn * 8;
            float bv0 = bias[col], bv1 = bias[col + 1];
            float2 o0 = make_float2(acc[tm][tn][0] + bv0, acc[tm][tn][1] + bv1);
            float2 o1 = make_float2(acc[tm][tn][2] + bv0, acc[tm][tn][3] + bv1);
            *reinterpret_cast<float2*>(Out + (size_t)row * Nst + col)       = o0;
            *reinterpret_cast<float2*>(Out + (size_t)(row + 8) * Nst + col) = o1;
        }
    }
}

// ---------------------------------------------------------------------------
// Sparse tree attention, scan-free + batched prefetch. One block per (b, n).
// Warp 0 assembles and rank-sorts the neighbor set (ascending m ->
// deterministic order identical to a reference scan). Each warp (= head)
// then prefetches up to 8 neighbors' C and S rows into registers in one
// MLP-parallel burst, and runs the online softmax register-resident in the
// same ascending order. Re-zeroes g_ncnt[bn] before exit (replay invariant).
// ---------------------------------------------------------------------------
__global__ __launch_bounds__(256) void tree_attn(const int* __restrict__ parent,
                                                 __half* __restrict__ aoh)
{
    const int bn = blockIdx.x;
    const int b  = bn >> 11;
    const int n  = bn & (SS - 1);

    __shared__ int fin[32];
    __shared__ int fcnt;

    const int tid  = threadIdx.x;
    const int warp = tid >> 5;
    const int lane = tid & 31;

    // P row load issued before the list barrier (independent of fin)
    const float* Prow = &g_PCS[(size_t)bn * NPROJ + warp * DD];
    const float p0 = Prow[lane];
    const float p1 = Prow[lane + 32];

    if (warp == 0) {
        int cnt = g_ncnt[bn];
        if (cnt > MAXCH) cnt = MAXCH;
        const int par_n = parent[b * SS + n];
        const bool inc_par = (parent[b * SS + par_n] != n);

        int mym = 0x7FFFFFFF;
        bool active = false;
        if (lane < cnt)                  { mym = g_nbr[bn * MAXCH + lane]; active = true; }
        else if (lane == cnt && inc_par) { mym = par_n;                    active = true; }

        int rank = 0;
        #pragma unroll
        for (int j = 0; j < 32; j++) {
            int mj = __shfl_sync(0xffffffffu, mym, j);
            rank += (mj < mym) ? 1 : 0;
        }
        if (active) fin[rank] = mym;
        if (lane == 0) fcnt = cnt + (inc_par ? 1 : 0);
    }
    __syncthreads();

    const int cnt = fcnt;
    const float scale = 0.125f;  // 1/sqrt(64)

    float m_run = -1e30f, l_run = 0.0f, a0 = 0.0f, a1 = 0.0f;

    for (int i0 = 0; i0 < cnt; i0 += 8) {
        const int nb = (cnt - i0 < 8) ? (cnt - i0) : 8;
        float c0[8], c1[8], s0[8], s1[8];
        // MLP-parallel burst: all loads independent
        #pragma unroll
        for (int j = 0; j < 8; j++) {
            if (j < nb) {
                int m = fin[i0 + j];
                const float* mb =
                    &g_PCS[((size_t)b * SS + m) * NPROJ + warp * DD];
                c0[j] = mb[512  + lane];
                c1[j] = mb[512  + lane + 32];
                s0[j] = mb[1024 + lane];
                s1[j] = mb[1024 + lane + 32];
            }
        }
        // Register-resident online softmax, ascending m
        #pragma unroll
        for (int j = 0; j < 8; j++) {
            if (j < nb) {
                float part = p0 * c0[j] + p1 * c1[j];
                #pragma unroll
                for (int off = 16; off; off >>= 1)
                    part += __shfl_xor_sync(0xffffffffu, part, off);
                float scr = part * scale;

                float m_new = fmaxf(m_run, scr);
                float corr  = __expf(m_run - m_new);
                float wgt   = __expf(scr - m_new);
                a0 = a0 * corr + wgt * s0[j];
                a1 = a1 * corr + wgt * s1[j];
                l_run = l_run * corr + wgt;
                m_run = m_new;
            }
        }
    }

    const float inv = 1.0f / l_run;
    const size_t obase = (size_t)bn * EE + warp * DD;
    aoh[obase + lane]      = __float2half_rn(a0 * inv);
    aoh[obase + lane + 32] = __float2half_rn(a1 * inv);

    // Restore the counter invariant for the next graph replay.
    if (tid == 0) g_ncnt[bn] = 0;
}

// ---------------------------------------------------------------------------
extern "C" void kernel_launch(void* const* d_in, const int* in_sizes, int n_in,
                              void* d_out, int out_size)
{
    (void)in_sizes; (void)n_in; (void)out_size;
    const float* x      = (const float*)d_in[0];
    const int*   parent = (const int*)  d_in[1];
    const float* Wp = (const float*)d_in[2];
    const float* bp = (const float*)d_in[3];
    const float* Wc = (const float*)d_in[4];
    const float* bc = (const float*)d_in[5];
    const float* Ws = (const float*)d_in[6];
    const float* bs = (const float*)d_in[7];
    const float* Wo = (const float*)d_in[8];
    const float* bo = (const float*)d_in[9];
    float* out = (float*)d_out;

    float *PCS, *bcat;
    __half *xh, *aoh, *Wt;
    cudaGetSymbolAddress((void**)&PCS,  g_PCS);
    cudaGetSymbolAddress((void**)&bcat, g_bcat);
    cudaGetSymbolAddress((void**)&xh,   g_xh);
    cudaGetSymbolAddress((void**)&aoh,  g_aoh);
    cudaGetSymbolAddress((void**)&Wt,   g_Wt);

    const int SMEM4 = 3 * (256 * GPITCH);   // 110592
    const int SMEM2 = 3 * (192 * GPITCH);   // 82944

    static bool attr_done = false;
    if (!attr_done) {
        cudaFuncSetAttribute(gemm_mma<4>,
            cudaFuncAttributeMaxDynamicSharedMemorySize, SMEM4);
        cudaFuncSetAttribute(gemm_mma<2>,
            cudaFuncAttributeMaxDynamicSharedMemorySize, SMEM2);
        attr_done = true;
    }

    prep_all<<<2064, 256>>>(Wp, Wc, Ws, Wo, bp, bc, bs, x, parent, Wt, bcat, xh);

    // Fused projection GEMM: N = 1536 (Wp|Wc|Ws transposed are contiguous)
    dim3 pgrid(NPROJ / 128, MT / 128);   // (12, 32) = 384 CTAs
    gemm_mma<4><<<pgrid, 256, SMEM4>>>(xh, Wt, bcat, PCS, NPROJ);

    tree_attn<<<MT, 256>>>(parent, aoh);

    dim3 ogrid(EE / 128, MT / 64);       // (4, 64) = 256 CTAs
    gemm_mma<2><<<ogrid, 256, SMEM2>>>(aoh, Wt + 3 * EE * EE, bo, out, EE);
}

// round 14
// speedup vs baseline: 1.1322x; 1.1322x over previous
#include <cuda_runtime.h>
#include <cuda_fp16.h>
#include <cstdint>

#define BB 2
#define SS 2048
#define EE 512
#define HH 8
#define DD 64
#define MT (BB*SS)     // 4096 rows
#define NPROJ 1536     // fused P|C|S output width
#define MAXCH 16       // max stored children per node

// ---------------------------------------------------------------------------
// Scratch (device globals: allocation-free per harness rules)
// ---------------------------------------------------------------------------
__device__ float  g_PCS[MT*NPROJ];                 // P|C|S fused, stride 1536
__device__ __align__(16) __half g_xh [MT*EE];
__device__ __align__(16) __half g_aoh[MT*EE];
__device__ __align__(16) __half g_Wt [4][EE*EE];   // transposed [N][K], fp16
__device__ float  g_bcat[NPROJ];                   // bp|bc|bs
__device__ int    g_nbr [MT*MAXCH];                // children lists (unordered)
__device__ int    g_ncnt[MT];                      // children counts (self-zeroing)

// ---------------------------------------------------------------------------
// Helpers (base-target PTX only: ldmatrix / mma.sync / cp.async)
// ---------------------------------------------------------------------------
__device__ __forceinline__ uint32_t smem_u32(const void* p) {
    uint32_t a;
    asm("{ .reg .u64 t; cvta.to.shared.u64 t, %1; cvt.u32.u64 %0, t; }"
        : "=r"(a) : "l"(p));
    return a;
}
__device__ __forceinline__ void ldsm4(uint32_t* r, uint32_t addr) {
    asm volatile("ldmatrix.sync.aligned.m8n8.x4.shared.b16 {%0,%1,%2,%3}, [%4];"
        : "=r"(r[0]), "=r"(r[1]), "=r"(r[2]), "=r"(r[3]) : "r"(addr));
}
__device__ __forceinline__ void mma16816(float* d, const uint32_t* a,
                                         uint32_t b0, uint32_t b1) {
    asm volatile("mma.sync.aligned.m16n8k16.row.col.f32.f16.f16.f32 "
        "{%0,%1,%2,%3}, {%4,%5,%6,%7}, {%8,%9}, {%0,%1,%2,%3};"
        : "+f"(d[0]), "+f"(d[1]), "+f"(d[2]), "+f"(d[3])
        : "r"(a[0]), "r"(a[1]), "r"(a[2]), "r"(a[3]), "r"(b0), "r"(b1));
}
__device__ __forceinline__ void cpasync16(uint32_t saddr, const void* g) {
    asm volatile("cp.async.cg.shared.global [%0], [%1], 16;"
                 :: "r"(saddr), "l"(g) : "memory");
}
#define CP_COMMIT() asm volatile("cp.async.commit_group;" ::: "memory")
#define CP_WAIT(n)  asm volatile("cp.async.wait_group %0;" :: "n"(n) : "memory")

// ---------------------------------------------------------------------------
// Combined prep: blocks [0,1024) transpose the 4 weights to fp16 [N][K];
// blocks [1024,2048) convert x to fp16; blocks [2048,2064) scatter children.
// (g_ncnt is zero on entry: zero-initialized at load, re-zeroed by tree_attn
//  at the end of every launch.)
// ---------------------------------------------------------------------------
__global__ __launch_bounds__(256) void prep_all(
    const float* __restrict__ Wp, const float* __restrict__ Wc,
    const float* __restrict__ Ws, const float* __restrict__ Wo,
    const float* __restrict__ bp, const float* __restrict__ bc,
    const float* __restrict__ bs, const float* __restrict__ x,
    const int* __restrict__ parent,
    __half* __restrict__ Wt, float* __restrict__ bcat,
    __half* __restrict__ xh)
{
    const int bid = blockIdx.x;
    const int tid = threadIdx.x;
    if (bid < 1024) {
        __shared__ float t[32][33];
        const int w    = bid >> 8;
        const int tile = bid & 255;
        const int k0 = (tile & 15) * 32, n0 = (tile >> 4) * 32;
        const float* W = (w == 0) ? Wp : (w == 1) ? Wc : (w == 2) ? Ws : Wo;
        __half* out = Wt + (size_t)w * EE * EE;
        const int tx = tid & 31;
        const int ty = tid >> 5;

        for (int j = ty; j < 32; j += 8)
            t[j][tx] = W[(size_t)(k0 + j) * EE + n0 + tx];
        __syncthreads();
        for (int j = ty; j < 32; j += 8)
            out[(size_t)(n0 + j) * EE + k0 + tx] = __float2half_rn(t[tx][j]);

        if (bid < 6) {
            int i = bid * 256 + tid;
            bcat[i] = (i < 512) ? bp[i] : (i < 1024) ? bc[i - 512] : bs[i - 1024];
        }
    } else if (bid < 2048) {
        const int base = (bid - 1024) * 512 + tid;
        #pragma unroll
        for (int r = 0; r < 2; r++) {
            int i = base + r * 256;
            float4 v = reinterpret_cast<const float4*>(x)[i];
            __half2 h01 = __halves2half2(__float2half_rn(v.x), __float2half_rn(v.y));
            __half2 h23 = __halves2half2(__float2half_rn(v.z), __float2half_rn(v.w));
            reinterpret_cast<__half2*>(xh)[i*2+0] = h01;
            reinterpret_cast<__half2*>(xh)[i*2+1] = h23;
        }
    } else {
        // Child scatter: node u = (b, m); append m to parent's child list.
        // Order within a list is nondeterministic (atomics) — tree_attn
        // sorts each list, restoring full determinism.
        const int u = (bid - 2048) * 256 + tid;     // 0..4095
        const int b = u >> 11;
        const int m = u & (SS - 1);
        const int p = parent[u];
        const int idx = b * SS + p;
        int pos = atomicAdd(&g_ncnt[idx], 1);
        if (pos < MAXCH) g_nbr[idx * MAXCH + pos] = m;
    }
}

// ---------------------------------------------------------------------------
// mma.sync fp16 GEMM (R8 config, FROZEN — used for the projection GEMM):
// Out[M,Nst] = A[M,512] @ Wt^T + bias. CTA (32*TM)x128, 8 warps.
// ---------------------------------------------------------------------------
#define GPITCH 144

template<int TM>
__global__ __launch_bounds__(256) void gemm_mma(
    const __half* __restrict__ Ah, const __half* __restrict__ Bh,
    const float* __restrict__ bias, float* __restrict__ Out, int Nst)
{
    constexpr int CTA_M  = 32 * TM;
    constexpr int TILE_A = CTA_M * GPITCH;
    constexpr int ROWS   = CTA_M + 128;
    constexpr int STAGE  = ROWS * GPITCH;
    constexpr int ITERS  = (ROWS * 8) / 256;

    extern __shared__ char smem[];
    const uint32_t sb = smem_u32(smem);
    const int tid  = threadIdx.x;
    const int wid  = tid >> 5;
    const int lane = tid & 31;
    const int wm   = wid & 1;
    const int wn   = wid >> 1;
    const int bm   = blockIdx.y * CTA_M;
    const int bn   = blockIdx.x * 128;

    float acc[TM][4][4];
    #pragma unroll
    for (int i = 0; i < TM; i++)
        #pragma unroll
        for (int j = 0; j < 4; j++)
            #pragma unroll
            for (int q = 0; q < 4; q++) acc[i][j][q] = 0.0f;

    auto load_stage = [&](int stg, int c) {
        const int kb = c * 64;
        #pragma unroll
        for (int j = 0; j < ITERS; j++) {
            int u   = j * 256 + tid;
            int row = u >> 3, cc = u & 7;
            bool isA = (row < CTA_M);
            uint32_t sa = sb + stg * STAGE
                        + (isA ? row * GPITCH : TILE_A + (row - CTA_M) * GPITCH)
                        + cc * 16;
            const __half* gp = isA ? Ah + (size_t)(bm + row) * EE
                                   : Bh + (size_t)(bn + row - CTA_M) * EE;
            cpasync16(sa, gp + kb + cc * 8);
        }
        CP_COMMIT();
    };

    load_stage(0, 0);
    load_stage(1, 1);

    const uint32_t lrow = (uint32_t)(lane & 15);
    const uint32_t lcol = (uint32_t)((lane >> 4) << 4);

    int stage = 0;
    for (int c = 0; c < 8; c++) {
        if (c < 6)      { load_stage((stage + 2) % 3, c + 2); CP_WAIT(2); }
        else if (c == 6){ CP_WAIT(1); }
        else            { CP_WAIT(0); }
        __syncthreads();

        const uint32_t stg = sb + stage * STAGE;
        const uint32_t abase = stg + (wm * 16 * TM + lrow) * GPITCH + lcol;
        const uint32_t bbase = stg + TILE_A + (wn * 32 + lrow) * GPITCH + lcol;

        uint32_t af[2][TM][4], bf[2][2][4];
        #pragma unroll
        for (int tm = 0; tm < TM; tm++) ldsm4(af[0][tm], abase + tm * 16 * GPITCH);
        #pragma unroll
        for (int t2 = 0; t2 < 2; t2++)  ldsm4(bf[0][t2], bbase + t2 * 16 * GPITCH);

        #pragma unroll
        for (int kk = 0; kk < 4; kk++) {
            const int cur = kk & 1, nxt = cur ^ 1;
            if (kk < 3) {
                const uint32_t ko = (kk + 1) * 32;
                #pragma unroll
                for (int tm = 0; tm < TM; tm++)
                    ldsm4(af[nxt][tm], abase + tm * 16 * GPITCH + ko);
                #pragma unroll
                for (int t2 = 0; t2 < 2; t2++)
                    ldsm4(bf[nxt][t2], bbase + t2 * 16 * GPITCH + ko);
            }
            #pragma unroll
            for (int tm = 0; tm < TM; tm++)
                #pragma unroll
                for (int tn = 0; tn < 4; tn++) {
                    const int t2 = tn >> 1, hi = tn & 1;
                    mma16816(acc[tm][tn], af[cur][tm],
                             bf[cur][t2][hi], bf[cur][t2][2 + hi]);
                }
        }
        __syncthreads();
        stage = (stage == 2) ? 0 : stage + 1;
    }

    const int r0 = bm + wm * 16 * TM + (lane >> 2);
    const int c0 = bn + wn * 32 + ((lane & 3) << 1);
    #pragma unroll
    for (int tm = 0; tm < TM; tm++) {
        #pragma unroll
        for (int tn = 0; tn < 4; tn++) {
            int row = r0 + tm * 16;
            int col = c0 + tn * 8;
            float bv0 = bias[col], bv1 = bias[col + 1];
            float2 o0 = make_float2(acc[tm][tn][0] + bv0, acc[tm][tn][1] + bv1);
            float2 o1 = make_float2(acc[tm][tn][2] + bv0, acc[tm][tn][3] + bv1);
            *reinterpret_cast<float2*>(Out + (size_t)row * Nst + col)       = o0;
            *reinterpret_cast<float2*>(Out + (size_t)(row + 8) * Nst + col) = o1;
        }
    }
}

// ---------------------------------------------------------------------------
// Out-projection GEMM: CTA 64x64, 4 warps (128 thr), warp tile 32x32
// (identical warp-level ldsm/mma pattern and K-order as gemm_mma ->
// bit-identical accumulation). grid (8,64) = 512 CTAs; stage 18.4KB x3
// = 55KB -> 4 CTAs/SM: ~2x concurrent loads per SM vs the 64x128 shape.
// ---------------------------------------------------------------------------
__global__ __launch_bounds__(128) void gemm_out(
    const __half* __restrict__ Ah, const __half* __restrict__ Bh,
    const float* __restrict__ bias, float* __restrict__ Out)
{
    constexpr int TILE_A = 64 * GPITCH;
    constexpr int STAGE  = 128 * GPITCH;    // 64 A rows + 64 B rows

    extern __shared__ char smem[];
    const uint32_t sb = smem_u32(smem);
    const int tid  = threadIdx.x;
    const int wid  = tid >> 5;
    const int lane = tid & 31;
    const int wm   = wid & 1;      // 2 warps over M (32 rows each)
    const int wn   = wid >> 1;     // 2 warps over N (32 cols each)
    const int bm   = blockIdx.y * 64;
    const int bn   = blockIdx.x * 64;

    float acc[2][4][4];
    #pragma unroll
    for (int i = 0; i < 2; i++)
        #pragma unroll
        for (int j = 0; j < 4; j++)
            #pragma unroll
            for (int q = 0; q < 4; q++) acc[i][j][q] = 0.0f;

    auto load_stage = [&](int stg, int c) {
        const int kb = c * 64;
        #pragma unroll
        for (int j = 0; j < 8; j++) {          // 128 rows * 8 chunks / 128 thr
            int u   = j * 128 + tid;
            int row = u >> 3, cc = u & 7;
            bool isA = (row < 64);
            uint32_t sa = sb + stg * STAGE
                        + (isA ? row * GPITCH : TILE_A + (row - 64) * GPITCH)
                        + cc * 16;
            const __half* gp = isA ? Ah + (size_t)(bm + row) * EE
                                   : Bh + (size_t)(bn + row - 64) * EE;
            cpasync16(sa, gp + kb + cc * 8);
        }
        CP_COMMIT();
    };

    load_stage(0, 0);
    load_stage(1, 1);

    const uint32_t lrow = (uint32_t)(lane & 15);
    const uint32_t lcol = (uint32_t)((lane >> 4) << 4);

    int stage = 0;
    for (int c = 0; c < 8; c++) {
        if (c < 6)      { load_stage((stage + 2) % 3, c + 2); CP_WAIT(2); }
        else if (c == 6){ CP_WAIT(1); }
        else            { CP_WAIT(0); }
        __syncthreads();

        const uint32_t stg = sb + stage * STAGE;
        const uint32_t abase = stg + (wm * 32 + lrow) * GPITCH + lcol;
        const uint32_t bbase = stg + TILE_A + (wn * 32 + lrow) * GPITCH + lcol;

        uint32_t af[2][2][4], bf[2][2][4];
        #pragma unroll
        for (int tm = 0; tm < 2; tm++) ldsm4(af[0][tm], abase + tm * 16 * GPITCH);
        #pragma unroll
        for (int t2 = 0; t2 < 2; t2++) ldsm4(bf[0][t2], bbase + t2 * 16 * GPITCH);

        #pragma unroll
        for (int kk = 0; kk < 4; kk++) {
            const int cur = kk & 1, nxt = cur ^ 1;
            if (kk < 3) {
                const uint32_t ko = (kk + 1) * 32;
                #pragma unroll
                for (int tm = 0; tm < 2; tm++)
                    ldsm4(af[nxt][tm], abase + tm * 16 * GPITCH + ko);
                #pragma unroll
                for (int t2 = 0; t2 < 2; t2++)
                    ldsm4(bf[nxt][t2], bbase + t2 * 16 * GPITCH + ko);
            }
            #pragma unroll
            for (int tm = 0; tm < 2; tm++)
                #pragma unroll
                for (int tn = 0; tn < 4; tn++) {
                    const int t2 = tn >> 1, hi = tn & 1;
                    mma16816(acc[tm][tn], af[cur][tm],
                             bf[cur][t2][hi], bf[cur][t2][2 + hi]);
                }
        }
        __syncthreads();
        stage = (stage == 2) ? 0 : stage + 1;
    }

    const int r0 = bm + wm * 32 + (lane >> 2);
    const int c0 = bn + wn * 32 + ((lane & 3) << 1);
    #pragma unroll
    for (int tm = 0; tm < 2; tm++) {
        #pragma unroll
        for (int tn = 0; tn < 4; tn++) {
            int row = r0 + tm * 16;
            int col = c0 + tn * 8;
            float bv0 = bias[col], bv1 = bias[col + 1];
            float2 o0 = make_float2(acc[tm][tn][0] + bv0, acc[tm][tn][1] + bv1);
            float2 o1 = make_float2(acc[tm][tn][2] + bv0, acc[tm][tn][3] + bv1);
            *reinterpret_cast<float2*>(Out + (size_t)row * EE + col)       = o0;
            *reinterpret_cast<float2*>(Out + (size_t)(row + 8) * EE + col) = o1;
        }
    }
}

// ---------------------------------------------------------------------------
// Sparse tree attention (R11 serial-loop version — highest-occupancy form).
// One block per (b, n). Warp 0 assembles + rank-sorts the neighbor set
// ascending-m (deterministic). Warp = head walks the list. Self-zeroes
// g_ncnt[bn] before exit (graph-replay invariant).
// ---------------------------------------------------------------------------
__global__ __launch_bounds__(256) void tree_attn(const int* __restrict__ parent,
                                                 __half* __restrict__ aoh)
{
    const int bn = blockIdx.x;
    const int b  = bn >> 11;
    const int n  = bn & (SS - 1);

    __shared__ int fin[32];
    __shared__ int fcnt;

    const int tid  = threadIdx.x;
    const int warp = tid >> 5;
    const int lane = tid & 31;

    if (warp == 0) {
        int cnt = g_ncnt[bn];
        if (cnt > MAXCH) cnt = MAXCH;
        const int par_n = parent[b * SS + n];
        const bool inc_par = (parent[b * SS + par_n] != n);

        int mym = 0x7FFFFFFF;
        bool active = false;
        if (lane < cnt)                  { mym = g_nbr[bn * MAXCH + lane]; active = true; }
        else if (lane == cnt && inc_par) { mym = par_n;                    active = true; }

        int rank = 0;
        #pragma unroll
        for (int j = 0; j < 32; j++) {
            int mj = __shfl_sync(0xffffffffu, mym, j);
            rank += (mj < mym) ? 1 : 0;
        }
        if (active) fin[rank] = mym;
        if (lane == 0) fcnt = cnt + (inc_par ? 1 : 0);
    }
    __syncthreads();

    const int cnt = fcnt;

    const float* Prow = &g_PCS[(size_t)bn * NPROJ + warp * DD];
    const float p0 = Prow[lane];
    const float p1 = Prow[lane + 32];

    float m_run = -1e30f, l_run = 0.0f, a0 = 0.0f, a1 = 0.0f;
    const float scale = 0.125f;  // 1/sqrt(64)

    for (int i = 0; i < cnt; i++) {
        int m = fin[i];
        const float* mbase = &g_PCS[((size_t)b * SS + m) * NPROJ + warp * DD];
        const float* Crow = mbase + 512;
        float part = p0 * Crow[lane] + p1 * Crow[lane + 32];
        #pragma unroll
        for (int off = 16; off; off >>= 1)
            part += __shfl_xor_sync(0xffffffffu, part, off);
        float scr = part * scale;

        float m_new = fmaxf(m_run, scr);
        float corr  = __expf(m_run - m_new);
        float wgt   = __expf(scr - m_new);
        const float* Srow = mbase + 1024;
        a0 = a0 * corr + wgt * Srow[lane];
        a1 = a1 * corr + wgt * Srow[lane + 32];
        l_run = l_run * corr + wgt;
        m_run = m_new;
    }

    const float inv = 1.0f / l_run;
    const size_t obase = (size_t)bn * EE + warp * DD;
    aoh[obase + lane]      = __float2half_rn(a0 * inv);
    aoh[obase + lane + 32] = __float2half_rn(a1 * inv);

    // Restore the counter invariant for the next graph replay.
    if (tid == 0) g_ncnt[bn] = 0;
}

// ---------------------------------------------------------------------------
extern "C" void kernel_launch(void* const* d_in, const int* in_sizes, int n_in,
                              void* d_out, int out_size)
{
    (void)in_sizes; (void)n_in; (void)out_size;
    const float* x      = (const float*)d_in[0];
    const int*   parent = (const int*)  d_in[1];
    const float* Wp = (const float*)d_in[2];
    const float* bp = (const float*)d_in[3];
    const float* Wc = (const float*)d_in[4];
    const float* bc = (const float*)d_in[5];
    const float* Ws = (const float*)d_in[6];
    const float* bs = (const float*)d_in[7];
    const float* Wo = (const float*)d_in[8];
    const float* bo = (const float*)d_in[9];
    float* out = (float*)d_out;

    float *PCS, *bcat;
    __half *xh, *aoh, *Wt;
    cudaGetSymbolAddress((void**)&PCS,  g_PCS);
    cudaGetSymbolAddress((void**)&bcat, g_bcat);
    cudaGetSymbolAddress((void**)&xh,   g_xh);
    cudaGetSymbolAddress((void**)&aoh,  g_aoh);
    cudaGetSymbolAddress((void**)&Wt,   g_Wt);

    const int SMEM4 = 3 * (256 * GPITCH);   // 110592
    const int SMEMO = 3 * (128 * GPITCH);   // 55296

    static bool attr_done = false;
    if (!attr_done) {
        cudaFuncSetAttribute(gemm_mma<4>,
            cudaFuncAttributeMaxDynamicSharedMemorySize, SMEM4);
        cudaFuncSetAttribute(gemm_out,
            cudaFuncAttributeMaxDynamicSharedMemorySize, SMEMO);
        attr_done = true;
    }

    prep_all<<<2064, 256>>>(Wp, Wc, Ws, Wo, bp, bc, bs, x, parent, Wt, bcat, xh);

    // Fused projection GEMM: N = 1536 (Wp|Wc|Ws transposed are contiguous)
    dim3 pgrid(NPROJ / 128, MT / 128);   // (12, 32) = 384 CTAs
    gemm_mma<4><<<pgrid, 256, SMEM4>>>(xh, Wt, bcat, PCS, NPROJ);

    tree_attn<<<MT, 256>>>(parent, aoh);

    dim3 ogrid(EE / 64, MT / 64);        // (8, 64) = 512 CTAs
    gemm_out<<<ogrid, 128, SMEMO>>>(aoh, Wt + 3 * EE * EE, bo, out);
}